// round 1
// baseline (speedup 1.0000x reference)
#include <cuda_runtime.h>

// Problem constants
#define BB     8
#define HH     64
#define WW     64
#define NPIX   (BB * HH * WW)      // 32768
#define DIM    192
#define QKVN   576                 // 3 * DIM
#define HEADSB 2
#define HEADD  32

// Scratch (device globals: allocation-free rule)
__device__ float g_qkv[(size_t)NPIX * QKVN];  // [pix][576]: branch*192 + qkv*64 + head*32 + d
__device__ float g_y[(size_t)NPIX * DIM];     // [pix][192]: branch*64 + head*32 + d

// ---------------------------------------------------------------------------
// QKV GEMM: C[m][n] = sum_k x[b][k][s] * w[n][k] + bias[n]
// m = (b, s=h*64+w), M=32768, N=576, K=192. x is CHW (stride 4096 over k).
// ---------------------------------------------------------------------------
__global__ __launch_bounds__(256) void qkv_gemm(const float* __restrict__ x,
                                                const float* __restrict__ w,
                                                const float* __restrict__ bias) {
    __shared__ float As[16][64];
    __shared__ float Bs[16][64];
    const int m0 = blockIdx.x * 64;
    const int n0 = blockIdx.y * 64;
    const int t  = threadIdx.x;
    const int tx = t & 15, ty = t >> 4;
    const int b  = m0 >> 12;
    const int s0 = m0 & 4095;
    const float* xb = x + (size_t)b * DIM * 4096 + s0;

    const int gB = t & 3;   // which float4 group of k
    const int jB = t >> 2;  // n index within tile

    float acc[4][4] = {};

    for (int k0 = 0; k0 < DIM; k0 += 16) {
        // A tile: coalesced along m (s), stride-4096 along k
        #pragma unroll
        for (int r = 0; r < 4; r++) {
            int idx = t + r * 256;
            int i  = idx & 63;
            int kk = idx >> 6;
            As[kk][i] = xb[(size_t)(k0 + kk) * 4096 + i];
        }
        // B tile: float4 along k within each weight row
        float4 b4 = *(const float4*)&w[(size_t)(n0 + jB) * DIM + k0 + gB * 4];
        Bs[gB * 4 + 0][jB] = b4.x;
        Bs[gB * 4 + 1][jB] = b4.y;
        Bs[gB * 4 + 2][jB] = b4.z;
        Bs[gB * 4 + 3][jB] = b4.w;
        __syncthreads();

        #pragma unroll
        for (int kk = 0; kk < 16; kk++) {
            float4 a4 = *(const float4*)&As[kk][ty * 4];
            float4 w4 = *(const float4*)&Bs[kk][tx * 4];
            float av[4] = {a4.x, a4.y, a4.z, a4.w};
            float bv[4] = {w4.x, w4.y, w4.z, w4.w};
            #pragma unroll
            for (int i = 0; i < 4; i++)
                #pragma unroll
                for (int j = 0; j < 4; j++)
                    acc[i][j] += av[i] * bv[j];
        }
        __syncthreads();
    }

    #pragma unroll
    for (int i = 0; i < 4; i++) {
        int m = m0 + ty * 4 + i;
        int n = n0 + tx * 4;
        float4 o;
        o.x = acc[i][0] + bias[n + 0];
        o.y = acc[i][1] + bias[n + 1];
        o.z = acc[i][2] + bias[n + 2];
        o.w = acc[i][3] + bias[n + 3];
        *(float4*)&g_qkv[(size_t)m * QKVN + n] = o;
    }
}

// ---------------------------------------------------------------------------
// NATTEN branch: one warp per (pixel, head). lane = head-dim channel.
// Online softmax over K*K neighbors; dot products via shfl reduction.
// ---------------------------------------------------------------------------
template<int K, int D, int BR>
__global__ __launch_bounds__(256) void natten_kernel(const float* __restrict__ rpb) {
    const int lane = threadIdx.x & 31;
    const int wid  = threadIdx.x >> 5;
    const int gid  = blockIdx.x * 8 + wid;      // NPIX * HEADSB total
    const int head = gid & 1;
    const int pix  = gid >> 1;
    const int w = pix & 63;
    const int h = (pix >> 6) & 63;
    const int b = pix >> 12;

    const float q =
        g_qkv[(size_t)pix * QKVN + BR * DIM + head * HEADD + lane] * 0.17677669529663687f;

    // NATTEN axis indices with dilation
    const int gh = h % D, iih = h / D;
    const int Lgh = (HH - gh + D - 1) / D;
    const int sth = min(max(iih - K / 2, 0), Lgh - K);
    const int gw = w % D, iiw = w / D;
    const int Lgw = (WW - gw + D - 1) / D;
    const int stw = min(max(iiw - K / 2, 0), Lgw - K);

    const float* rpbh = rpb + (size_t)head * (2 * K - 1) * (2 * K - 1)
                       + (size_t)(sth - iih + K - 1) * (2 * K - 1)
                       + (stw - iiw + K - 1);

    const float* basek = g_qkv + (size_t)(b * 4096) * QKVN + BR * DIM + 64 + head * HEADD + lane;

    float mx = -1e30f, l = 0.f, acc = 0.f;

    #pragma unroll
    for (int kh = 0; kh < K; kh++) {
        const int nh = gh + (sth + kh) * D;
        const float* rowk = basek + (size_t)(nh * 64) * QKVN;
        #pragma unroll
        for (int kw = 0; kw < K; kw++) {
            const int nw = gw + (stw + kw) * D;
            const float* kv = rowk + (size_t)nw * QKVN;
            const float kvl = kv[0];    // k channel
            const float vvl = kv[64];   // v channel (offset 64 within branch block)
            float s = q * kvl;
            s += __shfl_xor_sync(0xffffffffu, s, 16);
            s += __shfl_xor_sync(0xffffffffu, s, 8);
            s += __shfl_xor_sync(0xffffffffu, s, 4);
            s += __shfl_xor_sync(0xffffffffu, s, 2);
            s += __shfl_xor_sync(0xffffffffu, s, 1);
            s += rpbh[kh * (2 * K - 1) + kw];
            const float mn = fmaxf(mx, s);
            const float p  = __expf(s - mn);
            const float sc = __expf(mx - mn);
            l   = l * sc + p;
            acc = acc * sc + p * vvl;
            mx = mn;
        }
    }
    g_y[(size_t)pix * DIM + BR * 64 + head * HEADD + lane] = acc / l;
}

// ---------------------------------------------------------------------------
// Proj GEMM: out[b][n][s] = sum_k g_y[m][k] * w[n][k] + bias[n]
// M=32768, N=192, K=192. Smem transpose for coalesced CHW store.
// ---------------------------------------------------------------------------
__global__ __launch_bounds__(256) void proj_gemm(const float* __restrict__ w,
                                                 const float* __restrict__ bias,
                                                 float* __restrict__ out) {
    __shared__ float As[16][64];
    __shared__ float Bs[16][64];
    __shared__ float Ct[64][65];
    const int m0 = blockIdx.x * 64;
    const int n0 = blockIdx.y * 64;
    const int t  = threadIdx.x;
    const int tx = t & 15, ty = t >> 4;
    const int g4 = t & 3;
    const int i4 = t >> 2;

    float acc[4][4] = {};

    for (int k0 = 0; k0 < DIM; k0 += 16) {
        float4 a4 = *(const float4*)&g_y[(size_t)(m0 + i4) * DIM + k0 + g4 * 4];
        As[g4 * 4 + 0][i4] = a4.x;
        As[g4 * 4 + 1][i4] = a4.y;
        As[g4 * 4 + 2][i4] = a4.z;
        As[g4 * 4 + 3][i4] = a4.w;
        float4 b4 = *(const float4*)&w[(size_t)(n0 + i4) * DIM + k0 + g4 * 4];
        Bs[g4 * 4 + 0][i4] = b4.x;
        Bs[g4 * 4 + 1][i4] = b4.y;
        Bs[g4 * 4 + 2][i4] = b4.z;
        Bs[g4 * 4 + 3][i4] = b4.w;
        __syncthreads();

        #pragma unroll
        for (int kk = 0; kk < 16; kk++) {
            float4 aa = *(const float4*)&As[kk][ty * 4];
            float4 bb = *(const float4*)&Bs[kk][tx * 4];
            float av[4] = {aa.x, aa.y, aa.z, aa.w};
            float bv[4] = {bb.x, bb.y, bb.z, bb.w};
            #pragma unroll
            for (int i = 0; i < 4; i++)
                #pragma unroll
                for (int j = 0; j < 4; j++)
                    acc[i][j] += av[i] * bv[j];
        }
        __syncthreads();
    }

    // Transpose through smem (bias added here), then coalesced CHW store
    #pragma unroll
    for (int i = 0; i < 4; i++)
        #pragma unroll
        for (int j = 0; j < 4; j++)
            Ct[tx * 4 + j][ty * 4 + i] = acc[i][j] + bias[n0 + tx * 4 + j];
    __syncthreads();

    const int b  = m0 >> 12;
    const int s0 = m0 & 4095;
    float* ob = out + (size_t)b * DIM * 4096 + s0;
    #pragma unroll
    for (int r = 0; r < 16; r++) {
        int idx = t + r * 256;
        int nl = idx >> 6;
        int ml = idx & 63;
        ob[(size_t)(n0 + nl) * 4096 + ml] = Ct[nl][ml];
    }
}

// ---------------------------------------------------------------------------
extern "C" void kernel_launch(void* const* d_in, const int* in_sizes, int n_in,
                              void* d_out, int out_size) {
    const float* x      = (const float*)d_in[0];
    const float* qkv_w  = (const float*)d_in[1];
    const float* qkv_b  = (const float*)d_in[2];
    const float* proj_w = (const float*)d_in[3];
    const float* proj_b = (const float*)d_in[4];
    const float* rpb0   = (const float*)d_in[5];
    const float* rpb1   = (const float*)d_in[6];
    const float* rpb2   = (const float*)d_in[7];
    float* out = (float*)d_out;

    qkv_gemm<<<dim3(NPIX / 64, QKVN / 64), 256>>>(x, qkv_w, qkv_b);

    const int ablocks = (NPIX * HEADSB) / 8;   // 8 warps per block
    natten_kernel<3, 1, 0><<<ablocks, 256>>>(rpb0);
    natten_kernel<5, 2, 1><<<ablocks, 256>>>(rpb1);
    natten_kernel<7, 3, 2><<<ablocks, 256>>>(rpb2);

    proj_gemm<<<dim3(NPIX / 64, DIM / 64), 256>>>(proj_w, proj_b, out);
}

// round 2
// speedup vs baseline: 1.5054x; 1.5054x over previous
#include <cuda_runtime.h>

// Problem constants
#define BB     8
#define HH     64
#define WW     64
#define NPIX   (BB * HH * WW)      // 32768
#define DIM    192
#define QKVN   576                 // 3 * DIM
#define HEADSB 2
#define HEADD  32

// Scratch (device globals: allocation-free rule)
__device__ float g_qkv[(size_t)NPIX * QKVN];  // [pix][576]: branch*192 + qkv*64 + head*32 + d
__device__ float g_y[(size_t)NPIX * DIM];     // [pix][192]: branch*64 + head*32 + d

// ---------------------------------------------------------------------------
// QKV GEMM: C[m][n] = sum_k x[b][k][s] * w[n][k] + bias[n]
// M=32768 (tile 128), N=576 (tile 64), K=192. 256 threads, 8x4 micro-tile.
// ---------------------------------------------------------------------------
__global__ __launch_bounds__(256) void qkv_gemm(const float* __restrict__ x,
                                                const float* __restrict__ w,
                                                const float* __restrict__ bias) {
    __shared__ float As[16][128];
    __shared__ float Bs[16][64];
    const int m0 = blockIdx.x * 128;
    const int n0 = blockIdx.y * 64;
    const int t  = threadIdx.x;
    const int tx = t & 15;        // n group (4 cols)
    const int ty = t >> 4;        // m group (8 rows)
    const int b  = m0 >> 12;
    const int s0 = m0 & 4095;
    const float* xb = x + (size_t)b * DIM * 4096 + s0;

    const int gB = t & 3;   // float4 group of k for B loads
    const int jB = t >> 2;  // n row for B loads

    float acc[8][4] = {};

    for (int k0 = 0; k0 < DIM; k0 += 16) {
        // A tile 16k x 128m: coalesced along m, stride-4096 along k
        #pragma unroll
        for (int r = 0; r < 8; r++) {
            int idx = t + r * 256;
            int i  = idx & 127;
            int kk = idx >> 7;
            As[kk][i] = xb[(size_t)(k0 + kk) * 4096 + i];
        }
        // B tile 16k x 64n
        float4 b4 = *(const float4*)&w[(size_t)(n0 + jB) * DIM + k0 + gB * 4];
        Bs[gB * 4 + 0][jB] = b4.x;
        Bs[gB * 4 + 1][jB] = b4.y;
        Bs[gB * 4 + 2][jB] = b4.z;
        Bs[gB * 4 + 3][jB] = b4.w;
        __syncthreads();

        #pragma unroll
        for (int kk = 0; kk < 16; kk++) {
            float4 a0 = *(const float4*)&As[kk][ty * 8];
            float4 a1 = *(const float4*)&As[kk][ty * 8 + 4];
            float4 w4 = *(const float4*)&Bs[kk][tx * 4];
            float av[8] = {a0.x, a0.y, a0.z, a0.w, a1.x, a1.y, a1.z, a1.w};
            float bv[4] = {w4.x, w4.y, w4.z, w4.w};
            #pragma unroll
            for (int i = 0; i < 8; i++)
                #pragma unroll
                for (int j = 0; j < 4; j++)
                    acc[i][j] += av[i] * bv[j];
        }
        __syncthreads();
    }

    const int n = n0 + tx * 4;
    const float4 bb4 = *(const float4*)&bias[n];
    #pragma unroll
    for (int i = 0; i < 8; i++) {
        int m = m0 + ty * 8 + i;
        float4 o;
        o.x = acc[i][0] + bb4.x;
        o.y = acc[i][1] + bb4.y;
        o.z = acc[i][2] + bb4.z;
        o.w = acc[i][3] + bb4.w;
        *(float4*)&g_qkv[(size_t)m * QKVN + n] = o;
    }
}

// ---------------------------------------------------------------------------
// NATTEN branch: 8 lanes per (pixel, head); lane owns 4 channels (float4).
// Max-free softmax (scores bounded far below exp overflow): 1 exp/neighbor.
// ---------------------------------------------------------------------------
template<int K, int D, int BR>
__global__ __launch_bounds__(256) void natten_kernel(const float* __restrict__ rpb) {
    const int lane = threadIdx.x & 31;
    const int sl   = lane & 7;                       // channel group within unit
    const int gid  = (blockIdx.x * 256 + threadIdx.x) >> 3;  // unit id
    const int head = gid & 1;
    const int pix  = gid >> 1;
    const int w = pix & 63;
    const int h = (pix >> 6) & 63;
    const int b = pix >> 12;

    float4 q = *(const float4*)&g_qkv[(size_t)pix * QKVN + BR * DIM + head * HEADD + sl * 4];
    const float sc = 0.17677669529663687f;
    q.x *= sc; q.y *= sc; q.z *= sc; q.w *= sc;

    // NATTEN axis indices with dilation
    const int gh = h % D, iih = h / D;
    const int Lgh = (HH - gh + D - 1) / D;
    const int sth = min(max(iih - K / 2, 0), Lgh - K);
    const int gw = w % D, iiw = w / D;
    const int Lgw = (WW - gw + D - 1) / D;
    const int stw = min(max(iiw - K / 2, 0), Lgw - K);

    const float* rpbh = rpb + (size_t)head * (2 * K - 1) * (2 * K - 1)
                       + (size_t)(sth - iih + K - 1) * (2 * K - 1)
                       + (stw - iiw + K - 1);

    // k section base at neighbor (sth, stw)
    const float* base = g_qkv
        + (size_t)((b << 12) + (gh + sth * D) * 64 + (gw + stw * D)) * QKVN
        + BR * DIM + 64 + head * HEADD + sl * 4;

    const int strideW = D * QKVN;            // step one kw
    const int strideH = D * 64 * QKVN;       // step one kh

    float l = 0.f;
    float4 acc = {0.f, 0.f, 0.f, 0.f};

    #pragma unroll
    for (int kh = 0; kh < K; kh++) {
        const float* p = base + (size_t)kh * strideH;
        #pragma unroll
        for (int kw = 0; kw < K; kw++) {
            const float4 k4 = *(const float4*)p;
            const float4 v4 = *(const float4*)(p + 64);
            float s = q.x * k4.x + q.y * k4.y + q.z * k4.z + q.w * k4.w;
            s += __shfl_xor_sync(0xffffffffu, s, 4);
            s += __shfl_xor_sync(0xffffffffu, s, 2);
            s += __shfl_xor_sync(0xffffffffu, s, 1);
            const float pr = __expf(s + rpbh[kh * (2 * K - 1) + kw]);
            l += pr;
            acc.x += pr * v4.x;
            acc.y += pr * v4.y;
            acc.z += pr * v4.z;
            acc.w += pr * v4.w;
            p += strideW;
        }
    }
    const float rinv = __frcp_rn(l);
    float4 o;
    o.x = acc.x * rinv; o.y = acc.y * rinv; o.z = acc.z * rinv; o.w = acc.w * rinv;
    *(float4*)&g_y[(size_t)pix * DIM + BR * 64 + head * HEADD + sl * 4] = o;
}

// ---------------------------------------------------------------------------
// Proj GEMM: out[b][n][s] = sum_k g_y[m][k] * w[n][k] + bias[n]
// M=32768 (tile 128), N=192 (tile 64), K=192. Smem transpose for CHW store.
// ---------------------------------------------------------------------------
__global__ __launch_bounds__(256) void proj_gemm(const float* __restrict__ w,
                                                 const float* __restrict__ bias,
                                                 float* __restrict__ out) {
    __shared__ float As[16][128];
    __shared__ float Bs[16][64];
    __shared__ float Ct[64][129];
    const int m0 = blockIdx.x * 128;
    const int n0 = blockIdx.y * 64;
    const int t  = threadIdx.x;
    const int tx = t & 15, ty = t >> 4;
    const int g4 = t & 3;
    const int i4 = t >> 2;

    float acc[8][4] = {};

    for (int k0 = 0; k0 < DIM; k0 += 16) {
        // A tile: 128 rows of g_y, 16 k. 256 threads: 2 float4 each.
        #pragma unroll
        for (int r = 0; r < 2; r++) {
            int row = i4 + r * 64;
            float4 a4 = *(const float4*)&g_y[(size_t)(m0 + row) * DIM + k0 + g4 * 4];
            As[g4 * 4 + 0][row] = a4.x;
            As[g4 * 4 + 1][row] = a4.y;
            As[g4 * 4 + 2][row] = a4.z;
            As[g4 * 4 + 3][row] = a4.w;
        }
        float4 b4 = *(const float4*)&w[(size_t)(n0 + i4) * DIM + k0 + g4 * 4];
        Bs[g4 * 4 + 0][i4] = b4.x;
        Bs[g4 * 4 + 1][i4] = b4.y;
        Bs[g4 * 4 + 2][i4] = b4.z;
        Bs[g4 * 4 + 3][i4] = b4.w;
        __syncthreads();

        #pragma unroll
        for (int kk = 0; kk < 16; kk++) {
            float4 a0 = *(const float4*)&As[kk][ty * 8];
            float4 a1 = *(const float4*)&As[kk][ty * 8 + 4];
            float4 bb = *(const float4*)&Bs[kk][tx * 4];
            float av[8] = {a0.x, a0.y, a0.z, a0.w, a1.x, a1.y, a1.z, a1.w};
            float bv[4] = {bb.x, bb.y, bb.z, bb.w};
            #pragma unroll
            for (int i = 0; i < 8; i++)
                #pragma unroll
                for (int j = 0; j < 4; j++)
                    acc[i][j] += av[i] * bv[j];
        }
        __syncthreads();
    }

    // Transpose through smem (bias added), then coalesced CHW store
    #pragma unroll
    for (int i = 0; i < 8; i++)
        #pragma unroll
        for (int j = 0; j < 4; j++)
            Ct[tx * 4 + j][ty * 8 + i] = acc[i][j] + bias[n0 + tx * 4 + j];
    __syncthreads();

    const int b  = m0 >> 12;
    const int s0 = m0 & 4095;
    float* ob = out + (size_t)b * DIM * 4096 + s0;
    #pragma unroll
    for (int r = 0; r < 32; r++) {
        int idx = t + r * 256;
        int nl = idx >> 7;
        int ml = idx & 127;
        ob[(size_t)(n0 + nl) * 4096 + ml] = Ct[nl][ml];
    }
}

// ---------------------------------------------------------------------------
extern "C" void kernel_launch(void* const* d_in, const int* in_sizes, int n_in,
                              void* d_out, int out_size) {
    const float* x      = (const float*)d_in[0];
    const float* qkv_w  = (const float*)d_in[1];
    const float* qkv_b  = (const float*)d_in[2];
    const float* proj_w = (const float*)d_in[3];
    const float* proj_b = (const float*)d_in[4];
    const float* rpb0   = (const float*)d_in[5];
    const float* rpb1   = (const float*)d_in[6];
    const float* rpb2   = (const float*)d_in[7];
    float* out = (float*)d_out;

    qkv_gemm<<<dim3(NPIX / 128, QKVN / 64), 256>>>(x, qkv_w, qkv_b);

    const int ablocks = (NPIX * HEADSB) / 32;   // 32 units per block (8 lanes/unit)
    natten_kernel<3, 1, 0><<<ablocks, 256>>>(rpb0);
    natten_kernel<5, 2, 1><<<ablocks, 256>>>(rpb1);
    natten_kernel<7, 3, 2><<<ablocks, 256>>>(rpb2);

    proj_gemm<<<dim3(NPIX / 128, DIM / 64), 256>>>(proj_w, proj_b, out);
}

// round 3
// speedup vs baseline: 1.6049x; 1.0661x over previous
#include <cuda_runtime.h>

// Problem constants
#define BB     8
#define HH     64
#define WW     64
#define NPIX   (BB * HH * WW)      // 32768
#define DIM    192
#define QKVN   576                 // 3 * DIM
#define HEADSB 2
#define HEADD  32

typedef unsigned long long u64;

// Scratch (device globals: allocation-free rule)
__device__ float g_qkv[(size_t)NPIX * QKVN];  // [pix][576]
__device__ float g_y[(size_t)NPIX * DIM];     // [pix][192]

// ---- packed f32x2 helpers (sm_100+) --------------------------------------
__device__ __forceinline__ void ffma2(u64& d, u64 a, u64 b) {
    asm("fma.rn.f32x2 %0, %1, %2, %0;" : "+l"(d) : "l"(a), "l"(b));
}
__device__ __forceinline__ u64 dup2(float v) {
    u64 r; asm("mov.b64 %0, {%1, %1};" : "=l"(r) : "f"(v)); return r;
}
__device__ __forceinline__ u64 pk2(float lo, float hi) {
    u64 r; asm("mov.b64 %0, {%1, %2};" : "=l"(r) : "f"(lo), "f"(hi)); return r;
}
__device__ __forceinline__ void unpk2(u64 v, float& lo, float& hi) {
    asm("mov.b64 {%0, %1}, %2;" : "=f"(lo), "=f"(hi) : "l"(v));
}

// ---------------------------------------------------------------------------
// QKV GEMM: C[m][n] = sum_k x[b][k][s] * w[n][k] + bias[n]
// M=32768 (tile 128), N=576 (tile 64), K=192. 256 threads, 8x4 micro-tile,
// packed f32x2 FMA (pairs along m).
// ---------------------------------------------------------------------------
__global__ __launch_bounds__(256) void qkv_gemm(const float* __restrict__ x,
                                                const float* __restrict__ w,
                                                const float* __restrict__ bias) {
    __shared__ float As[16][128];
    __shared__ float Bs[16][64];
    const int m0 = blockIdx.x * 128;
    const int n0 = blockIdx.y * 64;
    const int t  = threadIdx.x;
    const int tx = t & 15;        // n group (4 cols)
    const int ty = t >> 4;        // m group (8 rows)
    const int b  = m0 >> 12;
    const int s0 = m0 & 4095;
    const float* xb = x + (size_t)b * DIM * 4096 + s0;

    const int gB = t & 3;
    const int jB = t >> 2;

    u64 acc2[4][4] = {};   // [m-pair][n]

    for (int k0 = 0; k0 < DIM; k0 += 16) {
        #pragma unroll
        for (int r = 0; r < 8; r++) {
            int idx = t + r * 256;
            int i  = idx & 127;
            int kk = idx >> 7;
            As[kk][i] = xb[(size_t)(k0 + kk) * 4096 + i];
        }
        float4 b4 = *(const float4*)&w[(size_t)(n0 + jB) * DIM + k0 + gB * 4];
        Bs[gB * 4 + 0][jB] = b4.x;
        Bs[gB * 4 + 1][jB] = b4.y;
        Bs[gB * 4 + 2][jB] = b4.z;
        Bs[gB * 4 + 3][jB] = b4.w;
        __syncthreads();

        #pragma unroll
        for (int kk = 0; kk < 16; kk++) {
            ulonglong2 a01 = *(const ulonglong2*)&As[kk][ty * 8];      // pairs (m0,m1),(m2,m3)
            ulonglong2 a23 = *(const ulonglong2*)&As[kk][ty * 8 + 4];  // pairs (m4,m5),(m6,m7)
            float4 bb = *(const float4*)&Bs[kk][tx * 4];
            u64 ap[4] = {a01.x, a01.y, a23.x, a23.y};
            u64 bd[4] = {dup2(bb.x), dup2(bb.y), dup2(bb.z), dup2(bb.w)};
            #pragma unroll
            for (int ip = 0; ip < 4; ip++)
                #pragma unroll
                for (int j = 0; j < 4; j++)
                    ffma2(acc2[ip][j], ap[ip], bd[j]);
        }
        __syncthreads();
    }

    const int n = n0 + tx * 4;
    const float4 bb4 = *(const float4*)&bias[n];
    #pragma unroll
    for (int ip = 0; ip < 4; ip++) {
        float lo[4], hi[4];
        #pragma unroll
        for (int j = 0; j < 4; j++) unpk2(acc2[ip][j], lo[j], hi[j]);
        int m = m0 + ty * 8 + ip * 2;
        float4 o0, o1;
        o0.x = lo[0] + bb4.x; o0.y = lo[1] + bb4.y; o0.z = lo[2] + bb4.z; o0.w = lo[3] + bb4.w;
        o1.x = hi[0] + bb4.x; o1.y = hi[1] + bb4.y; o1.z = hi[2] + bb4.z; o1.w = hi[3] + bb4.w;
        *(float4*)&g_qkv[(size_t)m * QKVN + n] = o0;
        *(float4*)&g_qkv[(size_t)(m + 1) * QKVN + n] = o1;
    }
}

// ---------------------------------------------------------------------------
// NATTEN: 8 lanes per (pixel, head); lane owns 4 channels.
// Row-batched: K k-loads -> K independent shfl/exp chains -> K v-loads.
// Max-free softmax (scores bounded; fp32 exp safe).
// ---------------------------------------------------------------------------
template<int K, int D, int BR>
__device__ __forceinline__ void natten_body(const float* __restrict__ rpb, int blk) {
    const int sl   = threadIdx.x & 7;
    const int gid  = (blk * 256 + threadIdx.x) >> 3;
    const int head = gid & 1;
    const int pix  = gid >> 1;
    const int w = pix & 63;
    const int h = (pix >> 6) & 63;
    const int b = pix >> 12;

    float4 q = *(const float4*)&g_qkv[(size_t)pix * QKVN + BR * DIM + head * HEADD + sl * 4];
    const float scq = 0.17677669529663687f;
    q.x *= scq; q.y *= scq; q.z *= scq; q.w *= scq;

    const int gh = h % D, iih = h / D;
    const int Lgh = (HH - gh + D - 1) / D;
    const int sth = min(max(iih - K / 2, 0), Lgh - K);
    const int gw = w % D, iiw = w / D;
    const int Lgw = (WW - gw + D - 1) / D;
    const int stw = min(max(iiw - K / 2, 0), Lgw - K);

    const float* rpbh = rpb + (size_t)head * (2 * K - 1) * (2 * K - 1)
                       + (size_t)(sth - iih + K - 1) * (2 * K - 1)
                       + (stw - iiw + K - 1);

    const float* base = g_qkv
        + (size_t)((b << 12) + (gh + sth * D) * 64 + (gw + stw * D)) * QKVN
        + BR * DIM + 64 + head * HEADD + sl * 4;

    const int strideW = D * QKVN;
    const int strideH = D * 64 * QKVN;

    float l = 0.f;
    u64 acc0 = 0, acc1 = 0;

    #pragma unroll
    for (int kh = 0; kh < K; kh++) {
        const float* p = base + (size_t)kh * strideH;
        float sarr[K];
        #pragma unroll
        for (int kw = 0; kw < K; kw++) {
            const float4 k4 = *(const float4*)(p + (size_t)kw * strideW);
            sarr[kw] = q.x * k4.x + q.y * k4.y + q.z * k4.z + q.w * k4.w;
        }
        #pragma unroll
        for (int kw = 0; kw < K; kw++) {
            float s = sarr[kw];
            s += __shfl_xor_sync(0xffffffffu, s, 4);
            s += __shfl_xor_sync(0xffffffffu, s, 2);
            s += __shfl_xor_sync(0xffffffffu, s, 1);
            sarr[kw] = __expf(s + rpbh[kh * (2 * K - 1) + kw]);
        }
        #pragma unroll
        for (int kw = 0; kw < K; kw++) {
            const float4 v4 = *(const float4*)(p + (size_t)kw * strideW + 64);
            const float pr = sarr[kw];
            l += pr;
            const u64 prd = dup2(pr);
            ffma2(acc0, pk2(v4.x, v4.y), prd);
            ffma2(acc1, pk2(v4.z, v4.w), prd);
        }
    }
    const float rinv = __frcp_rn(l);
    float4 o;
    unpk2(acc0, o.x, o.y);
    unpk2(acc1, o.z, o.w);
    o.x *= rinv; o.y *= rinv; o.z *= rinv; o.w *= rinv;
    *(float4*)&g_y[(size_t)pix * DIM + BR * 64 + head * HEADD + sl * 4] = o;
}

#define ABLOCKS (NPIX * HEADSB / 32)   // 2048 blocks per branch

__global__ __launch_bounds__(256) void natten_all(const float* __restrict__ rpb0,
                                                  const float* __restrict__ rpb1,
                                                  const float* __restrict__ rpb2) {
    const int bb = blockIdx.x;
    if (bb < ABLOCKS)          natten_body<3, 1, 0>(rpb0, bb);
    else if (bb < 2 * ABLOCKS) natten_body<5, 2, 1>(rpb1, bb - ABLOCKS);
    else                       natten_body<7, 3, 2>(rpb2, bb - 2 * ABLOCKS);
}

// ---------------------------------------------------------------------------
// Proj GEMM: out[b][n][s] = sum_k g_y[m][k] * w[n][k] + bias[n]
// M tile 128, N tile 64, K=192, f32x2 FMA, smem transpose for CHW store.
// ---------------------------------------------------------------------------
__global__ __launch_bounds__(256) void proj_gemm(const float* __restrict__ w,
                                                 const float* __restrict__ bias,
                                                 float* __restrict__ out) {
    __shared__ float As[16][128];
    __shared__ float Bs[16][64];
    __shared__ float Ct[64][129];
    const int m0 = blockIdx.x * 128;
    const int n0 = blockIdx.y * 64;
    const int t  = threadIdx.x;
    const int tx = t & 15, ty = t >> 4;
    const int g4 = t & 3;
    const int i4 = t >> 2;

    u64 acc2[4][4] = {};

    for (int k0 = 0; k0 < DIM; k0 += 16) {
        #pragma unroll
        for (int r = 0; r < 2; r++) {
            int row = i4 + r * 64;
            float4 a4 = *(const float4*)&g_y[(size_t)(m0 + row) * DIM + k0 + g4 * 4];
            As[g4 * 4 + 0][row] = a4.x;
            As[g4 * 4 + 1][row] = a4.y;
            As[g4 * 4 + 2][row] = a4.z;
            As[g4 * 4 + 3][row] = a4.w;
        }
        float4 b4 = *(const float4*)&w[(size_t)(n0 + i4) * DIM + k0 + g4 * 4];
        Bs[g4 * 4 + 0][i4] = b4.x;
        Bs[g4 * 4 + 1][i4] = b4.y;
        Bs[g4 * 4 + 2][i4] = b4.z;
        Bs[g4 * 4 + 3][i4] = b4.w;
        __syncthreads();

        #pragma unroll
        for (int kk = 0; kk < 16; kk++) {
            ulonglong2 a01 = *(const ulonglong2*)&As[kk][ty * 8];
            ulonglong2 a23 = *(const ulonglong2*)&As[kk][ty * 8 + 4];
            float4 bb = *(const float4*)&Bs[kk][tx * 4];
            u64 ap[4] = {a01.x, a01.y, a23.x, a23.y};
            u64 bd[4] = {dup2(bb.x), dup2(bb.y), dup2(bb.z), dup2(bb.w)};
            #pragma unroll
            for (int ip = 0; ip < 4; ip++)
                #pragma unroll
                for (int j = 0; j < 4; j++)
                    ffma2(acc2[ip][j], ap[ip], bd[j]);
        }
        __syncthreads();
    }

    const float4 bb4 = *(const float4*)&bias[n0 + tx * 4];
    const float bv[4] = {bb4.x, bb4.y, bb4.z, bb4.w};
    #pragma unroll
    for (int ip = 0; ip < 4; ip++) {
        float lo[4], hi[4];
        #pragma unroll
        for (int j = 0; j < 4; j++) {
            unpk2(acc2[ip][j], lo[j], hi[j]);
            Ct[tx * 4 + j][ty * 8 + ip * 2]     = lo[j] + bv[j];
            Ct[tx * 4 + j][ty * 8 + ip * 2 + 1] = hi[j] + bv[j];
        }
    }
    __syncthreads();

    const int b  = m0 >> 12;
    const int s0 = m0 & 4095;
    float* ob = out + (size_t)b * DIM * 4096 + s0;
    #pragma unroll
    for (int r = 0; r < 32; r++) {
        int idx = t + r * 256;
        int nl = idx >> 7;
        int ml = idx & 127;
        ob[(size_t)(n0 + nl) * 4096 + ml] = Ct[nl][ml];
    }
}

// ---------------------------------------------------------------------------
extern "C" void kernel_launch(void* const* d_in, const int* in_sizes, int n_in,
                              void* d_out, int out_size) {
    const float* x      = (const float*)d_in[0];
    const float* qkv_w  = (const float*)d_in[1];
    const float* qkv_b  = (const float*)d_in[2];
    const float* proj_w = (const float*)d_in[3];
    const float* proj_b = (const float*)d_in[4];
    const float* rpb0   = (const float*)d_in[5];
    const float* rpb1   = (const float*)d_in[6];
    const float* rpb2   = (const float*)d_in[7];
    float* out = (float*)d_out;

    qkv_gemm<<<dim3(NPIX / 128, QKVN / 64), 256>>>(x, qkv_w, qkv_b);
    natten_all<<<3 * ABLOCKS, 256>>>(rpb0, rpb1, rpb2);
    proj_gemm<<<dim3(NPIX / 128, DIM / 64), 256>>>(proj_w, proj_b, out);
}

// round 5
// speedup vs baseline: 2.3576x; 1.4690x over previous
#include <cuda_runtime.h>
#include <cuda_bf16.h>
#include <cstdint>

#define BB     8
#define HH     64
#define WW     64
#define NPIX   32768
#define DIM    192
#define QKVN   576
#define HEADSB 2
#define HEADD  32
#define KEXT   384        // hi(192) | lo(192) bf16

typedef unsigned long long u64;
typedef unsigned int u32;

// Scratch (device globals: allocation-free rule)
__device__ float         g_qkv[(size_t)NPIX * QKVN];
__device__ __nv_bfloat16 g_xe[(size_t)NPIX * KEXT];
__device__ __nv_bfloat16 g_ye[(size_t)NPIX * KEXT];
__device__ __nv_bfloat16 g_wqe[(size_t)QKVN * KEXT];
__device__ __nv_bfloat16 g_wpe[(size_t)DIM * KEXT];

// ---- f32x2 helpers (attention) -------------------------------------------
__device__ __forceinline__ void ffma2(u64& d, u64 a, u64 b) {
    asm("fma.rn.f32x2 %0, %1, %2, %0;" : "+l"(d) : "l"(a), "l"(b));
}
__device__ __forceinline__ u64 dup2(float v) {
    u64 r; asm("mov.b64 %0, {%1, %1};" : "=l"(r) : "f"(v)); return r;
}
__device__ __forceinline__ u64 pk2(float lo, float hi) {
    u64 r; asm("mov.b64 %0, {%1, %2};" : "=l"(r) : "f"(lo), "f"(hi)); return r;
}
__device__ __forceinline__ void unpk2(u64 v, float& lo, float& hi) {
    asm("mov.b64 {%0, %1}, %2;" : "=f"(lo), "=f"(hi) : "l"(v));
}

__device__ __forceinline__ u32 sToU32(const void* p) {
    u32 a;
    asm("{ .reg .u64 t; cvta.to.shared.u64 t, %1; cvt.u32.u64 %0, t; }" : "=r"(a) : "l"(p));
    return a;
}

// ---- warp MMA primitives (baseline sm_80+ PTX; no 'a' feature needed) ----
#define LDSM4(r, addr) \
    asm volatile("ldmatrix.sync.aligned.m8n8.x4.shared.b16 {%0,%1,%2,%3}, [%4];" \
                 : "=r"((r)[0]), "=r"((r)[1]), "=r"((r)[2]), "=r"((r)[3]) : "r"(addr))

__device__ __forceinline__ void hmma(float* c, const u32* a, u32 b0, u32 b1) {
    asm volatile(
        "mma.sync.aligned.m16n8k16.row.col.f32.bf16.bf16.f32 "
        "{%0,%1,%2,%3}, {%4,%5,%6,%7}, {%8,%9}, {%0,%1,%2,%3};"
        : "+f"(c[0]), "+f"(c[1]), "+f"(c[2]), "+f"(c[3])
        : "r"(a[0]), "r"(a[1]), "r"(a[2]), "r"(a[3]), "r"(b0), "r"(b1));
}

#define CPA16(s, g) asm volatile("cp.async.cg.shared.global [%0], [%1], 16;" :: "r"(s), "l"(g))
#define CPA_WAIT()  asm volatile("cp.async.commit_group;\ncp.async.wait_group 0;" ::: "memory")

// ---------------------------------------------------------------------------
// conv_x: x[b][k][s] fp32 -> g_xe[(b,s)][k]=hi, [192+k]=lo   (32x32 transpose)
// ---------------------------------------------------------------------------
__global__ __launch_bounds__(256) void conv_x(const float* __restrict__ x) {
    __shared__ float t[32][33];
    const int tx = threadIdx.x & 31, ty = threadIdx.x >> 5;
    const int s0 = blockIdx.x * 32, k0 = blockIdx.y * 32, b = blockIdx.z;
    const float* xb = x + ((size_t)b * DIM + k0) * 4096 + s0;
    #pragma unroll
    for (int r = 0; r < 4; r++)
        t[ty + 8 * r][tx] = xb[(size_t)(ty + 8 * r) * 4096 + tx];
    __syncthreads();
    #pragma unroll
    for (int r = 0; r < 4; r++) {
        const int sl = ty + 8 * r;
        const float v = t[tx][sl];
        const __nv_bfloat16 h = __float2bfloat16(v);
        const __nv_bfloat16 l = __float2bfloat16(v - __bfloat162float(h));
        __nv_bfloat16* row = g_xe + (size_t)((b << 12) + s0 + sl) * KEXT;
        row[k0 + tx]       = h;
        row[192 + k0 + tx] = l;
    }
}

__global__ __launch_bounds__(256) void conv_w(const float* __restrict__ wq,
                                              const float* __restrict__ wp) {
    int i = blockIdx.x * 256 + threadIdx.x;
    if (i < QKVN * DIM) {
        const int n = i / DIM, k = i % DIM;
        const float v = wq[i];
        const __nv_bfloat16 h = __float2bfloat16(v);
        const __nv_bfloat16 l = __float2bfloat16(v - __bfloat162float(h));
        g_wqe[(size_t)n * KEXT + k] = h;
        g_wqe[(size_t)n * KEXT + 192 + k] = l;
    } else {
        i -= QKVN * DIM;
        if (i < DIM * DIM) {
            const int n = i / DIM, k = i % DIM;
            const float v = wp[i];
            const __nv_bfloat16 h = __float2bfloat16(v);
            const __nv_bfloat16 l = __float2bfloat16(v - __bfloat162float(h));
            g_wpe[(size_t)n * KEXT + k] = h;
            g_wpe[(size_t)n * KEXT + 192 + k] = l;
        }
    }
}

// ---------------------------------------------------------------------------
// HMMA GEMM: C[m][n] = sum over 3 split terms of A_chunk · B_chunk.
// CTA 128x96, 8 warps (4m x 2n), warp tile 32x48, full K=384 in smem.
// EPI=0: g_qkv fp32 [m][576] + bias.  EPI=1: out CHW + bias (smem transpose).
// ---------------------------------------------------------------------------
#define MT 128
#define NT 96
#define SMB (MT * 768)                 // 98304 (A: 128 rows x 768B)
#define SM_TOT (SMB + NT * 768)        // 172032

template<int EPI>
__global__ __launch_bounds__(256) void hmma_gemm(const __nv_bfloat16* __restrict__ A,
                                                 const __nv_bfloat16* __restrict__ Bw,
                                                 const float* __restrict__ bias,
                                                 float* __restrict__ outp) {
    extern __shared__ char smem[];
    const u32 sb = sToU32(smem);
    const int tid = threadIdx.x;
    const int wid = tid >> 5, lane = tid & 31;
    const int m0 = blockIdx.x * MT;
    const int n0 = blockIdx.y * NT;

    // ---- fill A tile: 128 rows x 48 16B-chunks, XOR swizzle
    {
        const __nv_bfloat16* Ab = A + (size_t)m0 * KEXT;
        #pragma unroll
        for (int i = 0; i < 24; i++) {
            const int idx = tid + i * 256;
            const int m = idx / 48, c = idx % 48;
            CPA16(sb + m * 768 + ((c ^ (m & 7)) << 4), Ab + (size_t)m * KEXT + c * 8);
        }
        const __nv_bfloat16* Bb = Bw + (size_t)n0 * KEXT;
        #pragma unroll
        for (int i = 0; i < 18; i++) {
            const int idx = tid + i * 256;
            const int n = idx / 48, c = idx % 48;
            CPA16(sb + SMB + n * 768 + ((c ^ (n & 7)) << 4), Bb + (size_t)n * KEXT + c * 8);
        }
    }
    CPA_WAIT();
    __syncthreads();

    const int warpM = (wid >> 1) * 32;
    const int warpN = (wid & 1) * 48;
    const int lr = lane & 15;
    const int lh = lane >> 4;

    const u32 aBase = sb + (warpM + lr) * 768;
    const int asw   = lr & 7;
    u32 bBase[3]; int bsw[3];
    #pragma unroll
    for (int g = 0; g < 3; g++) {
        const int row = warpN + g * 16 + lr;
        bBase[g] = sb + SMB + row * 768;
        bsw[g]   = row & 7;
    }

    float acc[2][6][4] = {};

    #pragma unroll
    for (int t = 0; t < 3; t++) {
        const int akb = (t == 1) ? 24 : 0;
        const int bkb = (t == 2) ? 24 : 0;
        #pragma unroll
        for (int kk = 0; kk < 12; kk++) {
            const int ac = akb + kk * 2 + lh;
            u32 af0[4], af1[4];
            LDSM4(af0, aBase + ((ac ^ asw) << 4));
            LDSM4(af1, aBase + 16 * 768 + ((ac ^ asw) << 4));
            const int bc = bkb + kk * 2 + lh;
            u32 bf[3][4];
            #pragma unroll
            for (int g = 0; g < 3; g++)
                LDSM4(bf[g], bBase[g] + ((bc ^ bsw[g]) << 4));
            #pragma unroll
            for (int j = 0; j < 6; j++) {
                const int g = j >> 1, p = j & 1;
                hmma(acc[0][j], af0, bf[g][p], bf[g][p + 2]);
                hmma(acc[1][j], af1, bf[g][p], bf[g][p + 2]);
            }
        }
    }

    if (EPI == 0) {
        // direct fp32 stores into g_qkv [m][576]
        const int mrow = m0 + warpM + (lane >> 2);
        const int ncol = n0 + warpN + (lane & 3) * 2;
        #pragma unroll
        for (int mt = 0; mt < 2; mt++) {
            #pragma unroll
            for (int j = 0; j < 6; j++) {
                const int r = mrow + mt * 16;
                const int c = ncol + j * 8;
                const float b0 = bias[c], b1 = bias[c + 1];
                float2 v0 = {acc[mt][j][0] + b0, acc[mt][j][1] + b1};
                float2 v1 = {acc[mt][j][2] + b0, acc[mt][j][3] + b1};
                *(float2*)&g_qkv[(size_t)r * QKVN + c] = v0;
                *(float2*)&g_qkv[(size_t)(r + 8) * QKVN + c] = v1;
            }
        }
    } else {
        // smem transpose (reuse tile smem), coalesced CHW store
        __syncthreads();
        float* Ct = (float*)smem;  // [96][132]
        #pragma unroll
        for (int mt = 0; mt < 2; mt++) {
            #pragma unroll
            for (int j = 0; j < 6; j++) {
                const int rn = warpN + j * 8 + (lane & 3) * 2;
                const int rm = warpM + mt * 16 + (lane >> 2);
                Ct[rn * 132 + rm]           = acc[mt][j][0];
                Ct[(rn + 1) * 132 + rm]     = acc[mt][j][1];
                Ct[rn * 132 + rm + 8]       = acc[mt][j][2];
                Ct[(rn + 1) * 132 + rm + 8] = acc[mt][j][3];
            }
        }
        __syncthreads();
        const int b = m0 >> 12, s0 = m0 & 4095;
        float* ob = outp + ((size_t)b * DIM + n0) * 4096 + s0;
        #pragma unroll
        for (int i = 0; i < NT * MT / 256; i++) {
            const int idx = tid + i * 256;
            const int n = idx >> 7, m = idx & 127;
            ob[(size_t)n * 4096 + m] = Ct[n * 132 + m] + bias[n0 + n];
        }
    }
}

// ---------------------------------------------------------------------------
// NATTEN: 8 lanes per (pixel, head); lane owns 4 channels. Row-batched,
// max-free softmax. Output written as split bf16 (hi|lo) into g_ye.
// ---------------------------------------------------------------------------
template<int K, int D, int BR>
__device__ __forceinline__ void natten_body(const float* __restrict__ rpb, int blk) {
    const int sl   = threadIdx.x & 7;
    const int gid  = (blk * 256 + threadIdx.x) >> 3;
    const int head = gid & 1;
    const int pix  = gid >> 1;
    const int w = pix & 63;
    const int h = (pix >> 6) & 63;
    const int b = pix >> 12;

    float4 q = *(const float4*)&g_qkv[(size_t)pix * QKVN + BR * DIM + head * HEADD + sl * 4];
    const float scq = 0.17677669529663687f;
    q.x *= scq; q.y *= scq; q.z *= scq; q.w *= scq;

    const int gh = h % D, iih = h / D;
    const int Lgh = (HH - gh + D - 1) / D;
    const int sth = min(max(iih - K / 2, 0), Lgh - K);
    const int gw = w % D, iiw = w / D;
    const int Lgw = (WW - gw + D - 1) / D;
    const int stw = min(max(iiw - K / 2, 0), Lgw - K);

    const float* rpbh = rpb + (size_t)head * (2 * K - 1) * (2 * K - 1)
                       + (size_t)(sth - iih + K - 1) * (2 * K - 1)
                       + (stw - iiw + K - 1);

    const float* base = g_qkv
        + (size_t)((b << 12) + (gh + sth * D) * 64 + (gw + stw * D)) * QKVN
        + BR * DIM + 64 + head * HEADD + sl * 4;

    const int strideW = D * QKVN;
    const int strideH = D * 64 * QKVN;

    float l = 0.f;
    u64 acc0 = 0, acc1 = 0;

    #pragma unroll
    for (int kh = 0; kh < K; kh++) {
        const float* p = base + (size_t)kh * strideH;
        float sarr[K];
        #pragma unroll
        for (int kw = 0; kw < K; kw++) {
            const float4 k4 = *(const float4*)(p + (size_t)kw * strideW);
            sarr[kw] = q.x * k4.x + q.y * k4.y + q.z * k4.z + q.w * k4.w;
        }
        #pragma unroll
        for (int kw = 0; kw < K; kw++) {
            float s = sarr[kw];
            s += __shfl_xor_sync(0xffffffffu, s, 4);
            s += __shfl_xor_sync(0xffffffffu, s, 2);
            s += __shfl_xor_sync(0xffffffffu, s, 1);
            sarr[kw] = __expf(s + rpbh[kh * (2 * K - 1) + kw]);
        }
        #pragma unroll
        for (int kw = 0; kw < K; kw++) {
            const float4 v4 = *(const float4*)(p + (size_t)kw * strideW + 64);
            const float pr = sarr[kw];
            l += pr;
            const u64 prd = dup2(pr);
            ffma2(acc0, pk2(v4.x, v4.y), prd);
            ffma2(acc1, pk2(v4.z, v4.w), prd);
        }
    }
    const float rinv = __frcp_rn(l);
    float o[4];
    unpk2(acc0, o[0], o[1]);
    unpk2(acc1, o[2], o[3]);

    const int c = BR * 64 + head * HEADD + sl * 4;
    __nv_bfloat16 hi[4], lo[4];
    #pragma unroll
    for (int i = 0; i < 4; i++) {
        const float v = o[i] * rinv;
        hi[i] = __float2bfloat16(v);
        lo[i] = __float2bfloat16(v - __bfloat162float(hi[i]));
    }
    __nv_bfloat16* yr = g_ye + (size_t)pix * KEXT;
    *(u64*)(yr + c)       = *(const u64*)hi;
    *(u64*)(yr + 192 + c) = *(const u64*)lo;
}

#define ABLOCKS (NPIX * HEADSB / 32)   // 2048 blocks per branch

__global__ __launch_bounds__(256) void natten_all(const float* __restrict__ rpb0,
                                                  const float* __restrict__ rpb1,
                                                  const float* __restrict__ rpb2) {
    const int bb = blockIdx.x;
    if (bb < ABLOCKS)          natten_body<3, 1, 0>(rpb0, bb);
    else if (bb < 2 * ABLOCKS) natten_body<5, 2, 1>(rpb1, bb - ABLOCKS);
    else                       natten_body<7, 3, 2>(rpb2, bb - 2 * ABLOCKS);
}

// ---------------------------------------------------------------------------
extern "C" void kernel_launch(void* const* d_in, const int* in_sizes, int n_in,
                              void* d_out, int out_size) {
    const float* x      = (const float*)d_in[0];
    const float* qkv_w  = (const float*)d_in[1];
    const float* qkv_b  = (const float*)d_in[2];
    const float* proj_w = (const float*)d_in[3];
    const float* proj_b = (const float*)d_in[4];
    const float* rpb0   = (const float*)d_in[5];
    const float* rpb1   = (const float*)d_in[6];
    const float* rpb2   = (const float*)d_in[7];
    float* out = (float*)d_out;

    static int smem_set = 0;
    if (!smem_set) {
        cudaFuncSetAttribute(hmma_gemm<0>, cudaFuncAttributeMaxDynamicSharedMemorySize, SM_TOT);
        cudaFuncSetAttribute(hmma_gemm<1>, cudaFuncAttributeMaxDynamicSharedMemorySize, SM_TOT);
        smem_set = 1;
    }

    __nv_bfloat16* xe  = nullptr; cudaGetSymbolAddress((void**)&xe,  g_xe);
    __nv_bfloat16* ye  = nullptr; cudaGetSymbolAddress((void**)&ye,  g_ye);
    __nv_bfloat16* wqe = nullptr; cudaGetSymbolAddress((void**)&wqe, g_wqe);
    __nv_bfloat16* wpe = nullptr; cudaGetSymbolAddress((void**)&wpe, g_wpe);

    conv_x<<<dim3(128, 6, 8), 256>>>(x);
    conv_w<<<576, 256>>>(qkv_w, proj_w);

    hmma_gemm<0><<<dim3(NPIX / MT, QKVN / NT), 256, SM_TOT>>>(xe, wqe, qkv_b, nullptr);

    natten_all<<<3 * ABLOCKS, 256>>>(rpb0, rpb1, rpb2);

    hmma_gemm<1><<<dim3(NPIX / MT, DIM / NT), 256, SM_TOT>>>(ye, wpe, proj_b, out);
}